// round 3
// baseline (speedup 1.0000x reference)
#include <cuda_runtime.h>
#include <cuda_bf16.h>
#include <cstdint>

// Problem constants
#define DIMC    192
#define QKV_N   576
#define NWIN    144
#define NHEADS  6
#define HD      32
#define TOW     64
#define BATCH   30
#define MTOT    (BATCH * TOW * NWIN)   // 276480 rows
#define ATT_SCALE 0.17677669529663687f

// Scratch
static __device__ float g_qkv[(size_t)MTOT * QKV_N];
static __device__ float g_att[(size_t)MTOT * DIMC];
static __device__ float g_biasg[(size_t)NHEADS * TOW * NWIN * NWIN];

// ---------------------------------------------------------------------------
// tf32 helpers (portable mma.sync path; tcgen05 is 103a-gated and the harness
// builds compute_103 PTX, so it is unavailable)
// ---------------------------------------------------------------------------
__device__ __forceinline__ uint32_t f32_to_tf32(float x) {
    uint32_t r;
    asm("cvt.rna.tf32.f32 %0, %1;" : "=r"(r) : "f"(x));
    return r;
}

__device__ __forceinline__ void mma_tf32_16x8x8(
    float& c0, float& c1, float& c2, float& c3,
    uint32_t a0, uint32_t a1, uint32_t a2, uint32_t a3,
    uint32_t b0, uint32_t b1)
{
    asm volatile(
        "mma.sync.aligned.m16n8k8.row.col.f32.tf32.tf32.f32 "
        "{%0,%1,%2,%3}, {%4,%5,%6,%7}, {%8,%9}, {%0,%1,%2,%3};"
        : "+f"(c0), "+f"(c1), "+f"(c2), "+f"(c3)
        : "r"(a0), "r"(a1), "r"(a2), "r"(a3), "r"(b0), "r"(b1));
}

// ---------------------------------------------------------------------------
// tf32 mma.sync GEMM: C[M,N] = A[M,K] @ B[N,K]^T + bias[N]; cols<scaleCols *= scale
// CTA tile 128x64, BK=32, 256 threads = 8 warps (4m x 2n), warp tile 32x32.
// Requires M%128==0, N%64==0, K%32==0.
// ---------------------------------------------------------------------------
#define APITCH 36

__global__ __launch_bounds__(256)
void gemm_mma_kernel(const float* __restrict__ A, const float* __restrict__ B,
                     const float* __restrict__ bias, float* __restrict__ C,
                     int N, int K, int scaleCols, float scale)
{
    __shared__ uint32_t As[128 * APITCH];
    __shared__ uint32_t Bs[64 * APITCH];

    const int tid  = threadIdx.x;
    const int warp = tid >> 5, lane = tid & 31;
    const int wm   = warp & 3, wn = warp >> 2;          // 4 x 2 warp grid
    const int grp  = lane >> 2, tg = lane & 3;
    const int n0   = blockIdx.x * 64;
    const int m0   = blockIdx.y * 128;

    float c[2][4][4];   // [mtile][ntile][reg]
#pragma unroll
    for (int mt = 0; mt < 2; mt++)
#pragma unroll
        for (int nt = 0; nt < 4; nt++)
#pragma unroll
            for (int r = 0; r < 4; r++) c[mt][nt][r] = 0.f;

    const float* Ag = A + (size_t)m0 * K;
    const float* Bg = B + (size_t)n0 * K;

    for (int k0 = 0; k0 < K; k0 += 32) {
        // stage global loads (converted to tf32)
        float4 av[4], bv[2];
#pragma unroll
        for (int it = 0; it < 4; it++) {
            int idx = tid + it * 256;            // 1024 float4 = 128 rows x 8
            int row = idx >> 3, cc = idx & 7;
            av[it] = *(const float4*)&Ag[(size_t)row * K + k0 + cc * 4];
        }
#pragma unroll
        for (int it = 0; it < 2; it++) {
            int idx = tid + it * 256;            // 512 float4 = 64 rows x 8
            int row = idx >> 3, cc = idx & 7;
            bv[it] = *(const float4*)&Bg[(size_t)row * K + k0 + cc * 4];
        }
        __syncthreads();
#pragma unroll
        for (int it = 0; it < 4; it++) {
            int idx = tid + it * 256;
            int row = idx >> 3, cc = idx & 7;
            uint32_t* d = &As[row * APITCH + cc * 4];
            d[0] = f32_to_tf32(av[it].x); d[1] = f32_to_tf32(av[it].y);
            d[2] = f32_to_tf32(av[it].z); d[3] = f32_to_tf32(av[it].w);
        }
#pragma unroll
        for (int it = 0; it < 2; it++) {
            int idx = tid + it * 256;
            int row = idx >> 3, cc = idx & 7;
            uint32_t* d = &Bs[row * APITCH + cc * 4];
            d[0] = f32_to_tf32(bv[it].x); d[1] = f32_to_tf32(bv[it].y);
            d[2] = f32_to_tf32(bv[it].z); d[3] = f32_to_tf32(bv[it].w);
        }
        __syncthreads();

#pragma unroll
        for (int ks = 0; ks < 4; ks++) {
            const int k8 = ks * 8;
            uint32_t a[2][4];
#pragma unroll
            for (int mt = 0; mt < 2; mt++) {
                int rb = wm * 32 + mt * 16;
                a[mt][0] = As[(rb + grp) * APITCH + k8 + tg];
                a[mt][1] = As[(rb + grp + 8) * APITCH + k8 + tg];
                a[mt][2] = As[(rb + grp) * APITCH + k8 + tg + 4];
                a[mt][3] = As[(rb + grp + 8) * APITCH + k8 + tg + 4];
            }
#pragma unroll
            for (int nt = 0; nt < 4; nt++) {
                int nb = wn * 32 + nt * 8;
                uint32_t b0 = Bs[(nb + grp) * APITCH + k8 + tg];
                uint32_t b1 = Bs[(nb + grp) * APITCH + k8 + tg + 4];
#pragma unroll
                for (int mt = 0; mt < 2; mt++)
                    mma_tf32_16x8x8(c[mt][nt][0], c[mt][nt][1],
                                    c[mt][nt][2], c[mt][nt][3],
                                    a[mt][0], a[mt][1], a[mt][2], a[mt][3],
                                    b0, b1);
            }
        }
        __syncthreads();
    }

    // epilogue: +bias / scale, float2 stores
#pragma unroll
    for (int mt = 0; mt < 2; mt++) {
#pragma unroll
        for (int nt = 0; nt < 4; nt++) {
            int col = n0 + wn * 32 + nt * 8 + tg * 2;
            float b0 = bias[col], b1 = bias[col + 1];
            float s0 = (col     < scaleCols) ? scale : 1.f;
            float s1 = (col + 1 < scaleCols) ? scale : 1.f;
            int r0 = m0 + wm * 32 + mt * 16 + grp;
            float2 v0 = make_float2((c[mt][nt][0] + b0) * s0,
                                    (c[mt][nt][1] + b1) * s1);
            float2 v1 = make_float2((c[mt][nt][2] + b0) * s0,
                                    (c[mt][nt][3] + b1) * s1);
            *(float2*)&C[(size_t)r0 * N + col]       = v0;
            *(float2*)&C[(size_t)(r0 + 8) * N + col] = v1;
        }
    }
}

// ---------------------------------------------------------------------------
// Bias pre-gather
// ---------------------------------------------------------------------------
__global__ void bias_gather_kernel(const float* __restrict__ table,
                                   const int* __restrict__ pos)
{
    const int w = blockIdx.x, h = blockIdx.y;
    float* dst = g_biasg + (size_t)(h * TOW + w) * (NWIN * NWIN);
    for (int idx = threadIdx.x; idx < NWIN * NWIN; idx += blockDim.x) {
        int p = pos[idx];
        dst[idx] = table[((size_t)p * TOW + w) * NHEADS + h];
    }
}

// ---------------------------------------------------------------------------
// Attention (fp32 SIMT; mma.sync conversion is next round's change)
// ---------------------------------------------------------------------------
#define S_PITCH 145
#define ATTN_SMEM ((2 * 32 * 144 + 144 * 32 + 144 * S_PITCH) * 4)

__global__ __launch_bounds__(256)
void attn_kernel()
{
    extern __shared__ float smf[];
    float* Qt = smf;
    float* Kt = Qt + 32 * 144;
    float* Vs = Kt + 32 * 144;
    float* S  = Vs + 144 * 32;

    const int w = blockIdx.x, b = blockIdx.y, h = blockIdx.z;
    const int tid = threadIdx.x;
    const size_t base = (size_t)(b * TOW + w) * NWIN * QKV_N + h * HD;

    for (int idx = tid; idx < NWIN * 8; idx += 256) {
        int i = idx >> 3;
        int e0 = (idx & 7) * 4;
        const float* p = &g_qkv[base + (size_t)i * QKV_N + e0];
        float4 q  = *(const float4*)(p);
        float4 kk = *(const float4*)(p + 192);
        float4 vv = *(const float4*)(p + 384);
        Qt[(e0 + 0) * 144 + i] = q.x;  Qt[(e0 + 1) * 144 + i] = q.y;
        Qt[(e0 + 2) * 144 + i] = q.z;  Qt[(e0 + 3) * 144 + i] = q.w;
        Kt[(e0 + 0) * 144 + i] = kk.x; Kt[(e0 + 1) * 144 + i] = kk.y;
        Kt[(e0 + 2) * 144 + i] = kk.z; Kt[(e0 + 3) * 144 + i] = kk.w;
        *(float4*)&Vs[i * 32 + e0] = vv;
    }
    __syncthreads();

    const float* bptr = g_biasg + (size_t)(h * TOW + w) * (NWIN * NWIN);
    for (int t = tid; t < 36 * 36; t += 256) {
        int i0 = (t / 36) * 4;
        int j0 = (t % 36) * 4;
        float acc[4][4];
#pragma unroll
        for (int r = 0; r < 4; r++)
#pragma unroll
            for (int s = 0; s < 4; s++) acc[r][s] = 0.f;
#pragma unroll
        for (int e = 0; e < 32; e++) {
            float4 qa = *(const float4*)&Qt[e * 144 + i0];
            float4 kb = *(const float4*)&Kt[e * 144 + j0];
            float qr[4] = {qa.x, qa.y, qa.z, qa.w};
            float kc[4] = {kb.x, kb.y, kb.z, kb.w};
#pragma unroll
            for (int r = 0; r < 4; r++)
#pragma unroll
                for (int s = 0; s < 4; s++)
                    acc[r][s] = fmaf(qr[r], kc[s], acc[r][s]);
        }
#pragma unroll
        for (int r = 0; r < 4; r++) {
            float4 bv = *(const float4*)&bptr[(i0 + r) * 144 + j0];
            S[(i0 + r) * S_PITCH + j0 + 0] = acc[r][0] + bv.x;
            S[(i0 + r) * S_PITCH + j0 + 1] = acc[r][1] + bv.y;
            S[(i0 + r) * S_PITCH + j0 + 2] = acc[r][2] + bv.z;
            S[(i0 + r) * S_PITCH + j0 + 3] = acc[r][3] + bv.w;
        }
    }
    __syncthreads();

    const int warp = tid >> 5, lane = tid & 31;
    for (int r = warp; r < NWIN; r += 8) {
        float* row = &S[r * S_PITCH];
        float mx = -1e30f;
        for (int j = lane; j < NWIN; j += 32) mx = fmaxf(mx, row[j]);
#pragma unroll
        for (int o = 16; o; o >>= 1) mx = fmaxf(mx, __shfl_xor_sync(0xffffffffu, mx, o));
        float sum = 0.f;
        for (int j = lane; j < NWIN; j += 32) {
            float p = __expf(row[j] - mx);
            row[j] = p;
            sum += p;
        }
#pragma unroll
        for (int o = 16; o; o >>= 1) sum += __shfl_xor_sync(0xffffffffu, sum, o);
        float inv = 1.f / sum;
        for (int j = lane; j < NWIN; j += 32) row[j] *= inv;
    }
    __syncthreads();

    const size_t obase = (size_t)(b * TOW + w) * NWIN * DIMC + h * HD;
    for (int t = tid; t < 36 * 8; t += 256) {
        int i0 = (t >> 3) * 4;
        int e0 = (t & 7) * 4;
        float acc[4][4];
#pragma unroll
        for (int r = 0; r < 4; r++)
#pragma unroll
            for (int s = 0; s < 4; s++) acc[r][s] = 0.f;
#pragma unroll 4
        for (int j = 0; j < NWIN; j++) {
            float4 vv = *(const float4*)&Vs[j * 32 + e0];
            float p0 = S[(i0 + 0) * S_PITCH + j];
            float p1 = S[(i0 + 1) * S_PITCH + j];
            float p2 = S[(i0 + 2) * S_PITCH + j];
            float p3 = S[(i0 + 3) * S_PITCH + j];
            acc[0][0] = fmaf(p0, vv.x, acc[0][0]); acc[0][1] = fmaf(p0, vv.y, acc[0][1]);
            acc[0][2] = fmaf(p0, vv.z, acc[0][2]); acc[0][3] = fmaf(p0, vv.w, acc[0][3]);
            acc[1][0] = fmaf(p1, vv.x, acc[1][0]); acc[1][1] = fmaf(p1, vv.y, acc[1][1]);
            acc[1][2] = fmaf(p1, vv.z, acc[1][2]); acc[1][3] = fmaf(p1, vv.w, acc[1][3]);
            acc[2][0] = fmaf(p2, vv.x, acc[2][0]); acc[2][1] = fmaf(p2, vv.y, acc[2][1]);
            acc[2][2] = fmaf(p2, vv.z, acc[2][2]); acc[2][3] = fmaf(p2, vv.w, acc[2][3]);
            acc[3][0] = fmaf(p3, vv.x, acc[3][0]); acc[3][1] = fmaf(p3, vv.y, acc[3][1]);
            acc[3][2] = fmaf(p3, vv.z, acc[3][2]); acc[3][3] = fmaf(p3, vv.w, acc[3][3]);
        }
#pragma unroll
        for (int r = 0; r < 4; r++) {
            *(float4*)&g_att[obase + (size_t)(i0 + r) * DIMC + e0] =
                make_float4(acc[r][0], acc[r][1], acc[r][2], acc[r][3]);
        }
    }
}

// ---------------------------------------------------------------------------
extern "C" void kernel_launch(void* const* d_in, const int* in_sizes, int n_in,
                              void* d_out, int out_size)
{
    const float* x      = (const float*)d_in[0];
    const float* qkv_w  = (const float*)d_in[1];
    const float* qkv_b  = (const float*)d_in[2];
    const float* proj_w = (const float*)d_in[3];
    const float* proj_b = (const float*)d_in[4];
    const float* table  = (const float*)d_in[5];
    const int*   pos    = (const int*)d_in[6];
    float* out = (float*)d_out;

    float *qkv_s, *att_s;
    cudaGetSymbolAddress((void**)&qkv_s, g_qkv);
    cudaGetSymbolAddress((void**)&att_s, g_att);

    cudaFuncSetAttribute(attn_kernel, cudaFuncAttributeMaxDynamicSharedMemorySize,
                         ATTN_SMEM);

    // 1) fused QKV projection (mma.sync tf32; +bias, q scaled)
    {
        dim3 grid(QKV_N / 64, MTOT / 128);
        gemm_mma_kernel<<<grid, 256>>>(x, qkv_w, qkv_b, qkv_s,
                                       QKV_N, DIMC, DIMC, ATT_SCALE);
    }
    // 2) bias pre-gather
    {
        dim3 grid(TOW, NHEADS);
        bias_gather_kernel<<<grid, 256>>>(table, pos);
    }
    // 3) windowed attention
    {
        dim3 grid(TOW, BATCH, NHEADS);
        attn_kernel<<<grid, 256, ATTN_SMEM>>>();
    }
    // 4) output projection (mma.sync tf32)
    {
        dim3 grid(DIMC / 64, MTOT / 128);
        gemm_mma_kernel<<<grid, 256>>>(att_s, proj_w, proj_b, out,
                                       DIMC, DIMC, 0, 1.0f);
    }
}

// round 4
// speedup vs baseline: 2.0396x; 2.0396x over previous
#include <cuda_runtime.h>
#include <cuda_bf16.h>
#include <cstdint>

// Problem constants
#define DIMC    192
#define QKV_N   576
#define NWIN    144
#define NHEADS  6
#define HD      32
#define TOW     64
#define BATCH   30
#define MTOT    (BATCH * TOW * NWIN)   // 276480 rows
#define ATT_SCALE 0.17677669529663687f

// Scratch
static __device__ float g_qkv[(size_t)MTOT * QKV_N];
static __device__ float g_att[(size_t)MTOT * DIMC];
static __device__ float g_biasg[(size_t)NHEADS * TOW * NWIN * NWIN];

// ---------------------------------------------------------------------------
// tf32 mma.sync helpers (tcgen05 unavailable: harness builds compute_103 PTX)
// ---------------------------------------------------------------------------
__device__ __forceinline__ uint32_t f32_to_tf32(float x) {
    uint32_t r;
    asm("cvt.rna.tf32.f32 %0, %1;" : "=r"(r) : "f"(x));
    return r;
}

__device__ __forceinline__ void mma_tf32_16x8x8(
    float& c0, float& c1, float& c2, float& c3,
    uint32_t a0, uint32_t a1, uint32_t a2, uint32_t a3,
    uint32_t b0, uint32_t b1)
{
    asm volatile(
        "mma.sync.aligned.m16n8k8.row.col.f32.tf32.tf32.f32 "
        "{%0,%1,%2,%3}, {%4,%5,%6,%7}, {%8,%9}, {%0,%1,%2,%3};"
        : "+f"(c0), "+f"(c1), "+f"(c2), "+f"(c3)
        : "r"(a0), "r"(a1), "r"(a2), "r"(a3), "r"(b0), "r"(b1));
}

// ---------------------------------------------------------------------------
// tf32 mma.sync GEMM: C[M,N] = A[M,K] @ B[N,K]^T + bias[N]; cols<scaleCols *= scale
// CTA tile 128x64, BK=32, 256 threads = 8 warps (4m x 2n), warp tile 32x32.
// ---------------------------------------------------------------------------
#define APITCH 36

__global__ __launch_bounds__(256)
void gemm_mma_kernel(const float* __restrict__ A, const float* __restrict__ B,
                     const float* __restrict__ bias, float* __restrict__ C,
                     int N, int K, int scaleCols, float scale)
{
    __shared__ uint32_t As[128 * APITCH];
    __shared__ uint32_t Bs[64 * APITCH];

    const int tid  = threadIdx.x;
    const int warp = tid >> 5, lane = tid & 31;
    const int wm   = warp & 3, wn = warp >> 2;
    const int grp  = lane >> 2, tg = lane & 3;
    const int n0   = blockIdx.x * 64;
    const int m0   = blockIdx.y * 128;

    float c[2][4][4];
#pragma unroll
    for (int mt = 0; mt < 2; mt++)
#pragma unroll
        for (int nt = 0; nt < 4; nt++)
#pragma unroll
            for (int r = 0; r < 4; r++) c[mt][nt][r] = 0.f;

    const float* Ag = A + (size_t)m0 * K;
    const float* Bg = B + (size_t)n0 * K;

    for (int k0 = 0; k0 < K; k0 += 32) {
        float4 av[4], bv[2];
#pragma unroll
        for (int it = 0; it < 4; it++) {
            int idx = tid + it * 256;
            int row = idx >> 3, cc = idx & 7;
            av[it] = *(const float4*)&Ag[(size_t)row * K + k0 + cc * 4];
        }
#pragma unroll
        for (int it = 0; it < 2; it++) {
            int idx = tid + it * 256;
            int row = idx >> 3, cc = idx & 7;
            bv[it] = *(const float4*)&Bg[(size_t)row * K + k0 + cc * 4];
        }
        __syncthreads();
#pragma unroll
        for (int it = 0; it < 4; it++) {
            int idx = tid + it * 256;
            int row = idx >> 3, cc = idx & 7;
            uint32_t* d = &As[row * APITCH + cc * 4];
            d[0] = f32_to_tf32(av[it].x); d[1] = f32_to_tf32(av[it].y);
            d[2] = f32_to_tf32(av[it].z); d[3] = f32_to_tf32(av[it].w);
        }
#pragma unroll
        for (int it = 0; it < 2; it++) {
            int idx = tid + it * 256;
            int row = idx >> 3, cc = idx & 7;
            uint32_t* d = &Bs[row * APITCH + cc * 4];
            d[0] = f32_to_tf32(bv[it].x); d[1] = f32_to_tf32(bv[it].y);
            d[2] = f32_to_tf32(bv[it].z); d[3] = f32_to_tf32(bv[it].w);
        }
        __syncthreads();

#pragma unroll
        for (int ks = 0; ks < 4; ks++) {
            const int k8 = ks * 8;
            uint32_t a[2][4];
#pragma unroll
            for (int mt = 0; mt < 2; mt++) {
                int rb = wm * 32 + mt * 16;
                a[mt][0] = As[(rb + grp) * APITCH + k8 + tg];
                a[mt][1] = As[(rb + grp + 8) * APITCH + k8 + tg];
                a[mt][2] = As[(rb + grp) * APITCH + k8 + tg + 4];
                a[mt][3] = As[(rb + grp + 8) * APITCH + k8 + tg + 4];
            }
#pragma unroll
            for (int nt = 0; nt < 4; nt++) {
                int nb = wn * 32 + nt * 8;
                uint32_t b0 = Bs[(nb + grp) * APITCH + k8 + tg];
                uint32_t b1 = Bs[(nb + grp) * APITCH + k8 + tg + 4];
#pragma unroll
                for (int mt = 0; mt < 2; mt++)
                    mma_tf32_16x8x8(c[mt][nt][0], c[mt][nt][1],
                                    c[mt][nt][2], c[mt][nt][3],
                                    a[mt][0], a[mt][1], a[mt][2], a[mt][3],
                                    b0, b1);
            }
        }
        __syncthreads();
    }

#pragma unroll
    for (int mt = 0; mt < 2; mt++) {
#pragma unroll
        for (int nt = 0; nt < 4; nt++) {
            int col = n0 + wn * 32 + nt * 8 + tg * 2;
            float b0 = bias[col], b1 = bias[col + 1];
            float s0 = (col     < scaleCols) ? scale : 1.f;
            float s1 = (col + 1 < scaleCols) ? scale : 1.f;
            int r0 = m0 + wm * 32 + mt * 16 + grp;
            float2 v0 = make_float2((c[mt][nt][0] + b0) * s0,
                                    (c[mt][nt][1] + b1) * s1);
            float2 v1 = make_float2((c[mt][nt][2] + b0) * s0,
                                    (c[mt][nt][3] + b1) * s1);
            *(float2*)&C[(size_t)r0 * N + col]       = v0;
            *(float2*)&C[(size_t)(r0 + 8) * N + col] = v1;
        }
    }
}

// ---------------------------------------------------------------------------
// Bias pre-gather
// ---------------------------------------------------------------------------
__global__ void bias_gather_kernel(const float* __restrict__ table,
                                   const int* __restrict__ pos)
{
    const int w = blockIdx.x, h = blockIdx.y;
    float* dst = g_biasg + (size_t)(h * TOW + w) * (NWIN * NWIN);
    for (int idx = threadIdx.x; idx < NWIN * NWIN; idx += blockDim.x) {
        int p = pos[idx];
        dst[idx] = table[((size_t)p * TOW + w) * NHEADS + h];
    }
}

// ---------------------------------------------------------------------------
// Tensor-core attention: one CTA per (b,w,h), 288 threads = 9 warps,
// each warp owns a 16-row stripe of the 144-token window.
// smem (words): Qs[144*36] Ks[144*36] (tf32), Vt[32*148] (tf32, transposed),
//               S[144*148] (fp32 scores -> tf32 probabilities in-place)
// ---------------------------------------------------------------------------
#define ATTN_THREADS 288
#define QKP 36
#define SP  148
#define QS_OFF 0
#define KS_OFF (NWIN * QKP)
#define VT_OFF (KS_OFF + NWIN * QKP)
#define SS_OFF (VT_OFF + HD * SP)
#define ATTN_SMEM_B ((SS_OFF + NWIN * SP) * 4)

__global__ __launch_bounds__(ATTN_THREADS)
void attn_mma_kernel()
{
    extern __shared__ uint32_t smw[];
    uint32_t* Qs = smw + QS_OFF;
    uint32_t* Ks = smw + KS_OFF;
    uint32_t* Vt = smw + VT_OFF;
    float*    S  = (float*)(smw + SS_OFF);
    uint32_t* Su = smw + SS_OFF;

    const int w = blockIdx.x, b = blockIdx.y, h = blockIdx.z;
    const int tid  = threadIdx.x;
    const int warp = tid >> 5, lane = tid & 31;
    const int grp  = lane >> 2, tg = lane & 3;
    const int rb   = warp * 16;

    const size_t base = (size_t)(b * TOW + w) * NWIN * QKV_N + h * HD;

    // Load Q,K (row-major tf32) and V (transposed tf32)
    for (int idx = tid; idx < NWIN * 8; idx += ATTN_THREADS) {
        int i = idx >> 3, e0 = (idx & 7) * 4;
        const float* p = &g_qkv[base + (size_t)i * QKV_N + e0];
        float4 q = *(const float4*)(p);
        float4 k = *(const float4*)(p + 192);
        float4 v = *(const float4*)(p + 384);
        uint32_t* qd = &Qs[i * QKP + e0];
        qd[0] = f32_to_tf32(q.x); qd[1] = f32_to_tf32(q.y);
        qd[2] = f32_to_tf32(q.z); qd[3] = f32_to_tf32(q.w);
        uint32_t* kd = &Ks[i * QKP + e0];
        kd[0] = f32_to_tf32(k.x); kd[1] = f32_to_tf32(k.y);
        kd[2] = f32_to_tf32(k.z); kd[3] = f32_to_tf32(k.w);
        Vt[(e0 + 0) * SP + i] = f32_to_tf32(v.x);
        Vt[(e0 + 1) * SP + i] = f32_to_tf32(v.y);
        Vt[(e0 + 2) * SP + i] = f32_to_tf32(v.z);
        Vt[(e0 + 3) * SP + i] = f32_to_tf32(v.w);
    }
    __syncthreads();

    // S = Q K^T + bias
    const float* bptr = g_biasg + (size_t)(h * TOW + w) * (NWIN * NWIN);
#pragma unroll 2
    for (int nt = 0; nt < 18; nt++) {
        const int nb = nt * 8;
        float c0 = 0.f, c1 = 0.f, c2 = 0.f, c3 = 0.f;
#pragma unroll
        for (int ks = 0; ks < 4; ks++) {
            const int k8 = ks * 8;
            uint32_t a0 = Qs[(rb + grp) * QKP + k8 + tg];
            uint32_t a1 = Qs[(rb + grp + 8) * QKP + k8 + tg];
            uint32_t a2 = Qs[(rb + grp) * QKP + k8 + tg + 4];
            uint32_t a3 = Qs[(rb + grp + 8) * QKP + k8 + tg + 4];
            uint32_t b0 = Ks[(nb + grp) * QKP + k8 + tg];
            uint32_t b1 = Ks[(nb + grp) * QKP + k8 + tg + 4];
            mma_tf32_16x8x8(c0, c1, c2, c3, a0, a1, a2, a3, b0, b1);
        }
        const int col = nb + tg * 2;
        float2 bv0 = *(const float2*)&bptr[(rb + grp) * NWIN + col];
        float2 bv1 = *(const float2*)&bptr[(rb + grp + 8) * NWIN + col];
        *(float2*)&S[(rb + grp) * SP + col]     = make_float2(c0 + bv0.x, c1 + bv0.y);
        *(float2*)&S[(rb + grp + 8) * SP + col] = make_float2(c2 + bv1.x, c3 + bv1.y);
    }
    __syncthreads();

    // Softmax per row (warp handles its 16 rows); write tf32 probabilities in-place
    for (int r = 0; r < 16; r++) {
        float* row = &S[(rb + r) * SP];
        float mx = -1e30f;
        for (int j = lane; j < NWIN; j += 32) mx = fmaxf(mx, row[j]);
#pragma unroll
        for (int o = 16; o; o >>= 1) mx = fmaxf(mx, __shfl_xor_sync(0xffffffffu, mx, o));
        float pv[5];
        float sum = 0.f;
        int cnt = 0;
        for (int j = lane; j < NWIN; j += 32) {
            float p = __expf(row[j] - mx);
            pv[cnt++] = p;
            sum += p;
        }
#pragma unroll
        for (int o = 16; o; o >>= 1) sum += __shfl_xor_sync(0xffffffffu, sum, o);
        float inv = 1.f / sum;
        cnt = 0;
        uint32_t* rowu = &Su[(rb + r) * SP];
        for (int j = lane; j < NWIN; j += 32) rowu[j] = f32_to_tf32(pv[cnt++] * inv);
    }
    __syncthreads();

    // O = P V  (warp: 16 rows x 32 cols, K = 144)
    float c[4][4];
#pragma unroll
    for (int nt = 0; nt < 4; nt++)
#pragma unroll
        for (int r = 0; r < 4; r++) c[nt][r] = 0.f;

#pragma unroll 2
    for (int kk = 0; kk < 18; kk++) {
        const int k8 = kk * 8;
        uint32_t a0 = Su[(rb + grp) * SP + k8 + tg];
        uint32_t a1 = Su[(rb + grp + 8) * SP + k8 + tg];
        uint32_t a2 = Su[(rb + grp) * SP + k8 + tg + 4];
        uint32_t a3 = Su[(rb + grp + 8) * SP + k8 + tg + 4];
#pragma unroll
        for (int nt = 0; nt < 4; nt++) {
            uint32_t b0 = Vt[(nt * 8 + grp) * SP + k8 + tg];
            uint32_t b1 = Vt[(nt * 8 + grp) * SP + k8 + tg + 4];
            mma_tf32_16x8x8(c[nt][0], c[nt][1], c[nt][2], c[nt][3],
                            a0, a1, a2, a3, b0, b1);
        }
    }

    const size_t obase = (size_t)(b * TOW + w) * NWIN * DIMC + h * HD;
#pragma unroll
    for (int nt = 0; nt < 4; nt++) {
        const int col = nt * 8 + tg * 2;
        *(float2*)&g_att[obase + (size_t)(rb + grp) * DIMC + col] =
            make_float2(c[nt][0], c[nt][1]);
        *(float2*)&g_att[obase + (size_t)(rb + grp + 8) * DIMC + col] =
            make_float2(c[nt][2], c[nt][3]);
    }
}

// ---------------------------------------------------------------------------
extern "C" void kernel_launch(void* const* d_in, const int* in_sizes, int n_in,
                              void* d_out, int out_size)
{
    const float* x      = (const float*)d_in[0];
    const float* qkv_w  = (const float*)d_in[1];
    const float* qkv_b  = (const float*)d_in[2];
    const float* proj_w = (const float*)d_in[3];
    const float* proj_b = (const float*)d_in[4];
    const float* table  = (const float*)d_in[5];
    const int*   pos    = (const int*)d_in[6];
    float* out = (float*)d_out;

    float *qkv_s, *att_s;
    cudaGetSymbolAddress((void**)&qkv_s, g_qkv);
    cudaGetSymbolAddress((void**)&att_s, g_att);

    cudaFuncSetAttribute(attn_mma_kernel, cudaFuncAttributeMaxDynamicSharedMemorySize,
                         ATTN_SMEM_B);

    // 1) fused QKV projection (mma.sync tf32; +bias, q scaled)
    {
        dim3 grid(QKV_N / 64, MTOT / 128);
        gemm_mma_kernel<<<grid, 256>>>(x, qkv_w, qkv_b, qkv_s,
                                       QKV_N, DIMC, DIMC, ATT_SCALE);
    }
    // 2) bias pre-gather
    {
        dim3 grid(TOW, NHEADS);
        bias_gather_kernel<<<grid, 256>>>(table, pos);
    }
    // 3) windowed attention (tensor-core)
    {
        dim3 grid(TOW, BATCH, NHEADS);
        attn_mma_kernel<<<grid, ATTN_THREADS, ATTN_SMEM_B>>>();
    }
    // 4) output projection (mma.sync tf32)
    {
        dim3 grid(DIMC / 64, MTOT / 128);
        gemm_mma_kernel<<<grid, 256>>>(att_s, proj_w, proj_b, out,
                                       DIMC, DIMC, 0, 1.0f);
    }
}

// round 5
// speedup vs baseline: 2.3897x; 1.1716x over previous
#include <cuda_runtime.h>
#include <cuda_bf16.h>
#include <cstdint>

// Problem constants
#define DIMC    192
#define QKV_N   576
#define NWIN    144
#define NHEADS  6
#define HD      32
#define TOW     64
#define BATCH   30
#define MTOT    (BATCH * TOW * NWIN)   // 276480 rows
#define ATT_SCALE 0.17677669529663687f

// Scratch
static __device__ float g_qkv[(size_t)MTOT * QKV_N];
static __device__ float g_att[(size_t)MTOT * DIMC];
static __device__ float g_biasg[(size_t)NHEADS * TOW * NWIN * NWIN];

// ---------------------------------------------------------------------------
// tf32 mma.sync helpers (tcgen05 unavailable: harness builds compute_103 PTX)
// ---------------------------------------------------------------------------
__device__ __forceinline__ uint32_t f32_to_tf32(float x) {
    uint32_t r;
    asm("cvt.rna.tf32.f32 %0, %1;" : "=r"(r) : "f"(x));
    return r;
}

__device__ __forceinline__ void mma_tf32_16x8x8(
    float& c0, float& c1, float& c2, float& c3,
    uint32_t a0, uint32_t a1, uint32_t a2, uint32_t a3,
    uint32_t b0, uint32_t b1)
{
    asm volatile(
        "mma.sync.aligned.m16n8k8.row.col.f32.tf32.tf32.f32 "
        "{%0,%1,%2,%3}, {%4,%5,%6,%7}, {%8,%9}, {%0,%1,%2,%3};"
        : "+f"(c0), "+f"(c1), "+f"(c2), "+f"(c3)
        : "r"(a0), "r"(a1), "r"(a2), "r"(a3), "r"(b0), "r"(b1));
}

// ---------------------------------------------------------------------------
// tf32 mma.sync GEMM, double-buffered smem.
// C[M,N] = A[M,K] @ B[N,K]^T + bias[N]; cols<scaleCols *= scale
// CTA tile 128x64, BK=32, 256 threads = 8 warps (4m x 2n), warp tile 32x32.
// Dynamic smem: As[2][128*36] + Bs[2][64*36]  (55296 B)
// ---------------------------------------------------------------------------
#define APITCH 36
#define AS_WORDS (128 * APITCH)
#define BS_WORDS (64 * APITCH)
#define GEMM_SMEM_B ((2 * AS_WORDS + 2 * BS_WORDS) * 4)

__global__ __launch_bounds__(256, 2)
void gemm_mma_kernel(const float* __restrict__ A, const float* __restrict__ B,
                     const float* __restrict__ bias, float* __restrict__ C,
                     int N, int K, int scaleCols, float scale)
{
    extern __shared__ uint32_t gsm[];
    uint32_t* AsBase = gsm;
    uint32_t* BsBase = gsm + 2 * AS_WORDS;

    const int tid  = threadIdx.x;
    const int warp = tid >> 5, lane = tid & 31;
    const int wm   = warp & 3, wn = warp >> 2;
    const int grp  = lane >> 2, tg = lane & 3;
    const int n0   = blockIdx.x * 64;
    const int m0   = blockIdx.y * 128;

    float c[2][4][4];
#pragma unroll
    for (int mt = 0; mt < 2; mt++)
#pragma unroll
        for (int nt = 0; nt < 4; nt++)
#pragma unroll
            for (int r = 0; r < 4; r++) c[mt][nt][r] = 0.f;

    const float* Ag = A + (size_t)m0 * K;
    const float* Bg = B + (size_t)n0 * K;

    const int arow = tid >> 3, acol = (tid & 7) * 4;   // A: 4 chunks of 32 rows
    const int brow = tid >> 3, bcol = (tid & 7) * 4;   // B: 2 chunks of 32 rows

    // prologue: load k0=0, convert, store buffer 0
    {
        float4 av[4], bv[2];
#pragma unroll
        for (int it = 0; it < 4; it++)
            av[it] = *(const float4*)&Ag[(size_t)(arow + it * 32) * K + acol];
#pragma unroll
        for (int it = 0; it < 2; it++)
            bv[it] = *(const float4*)&Bg[(size_t)(brow + it * 32) * K + bcol];
#pragma unroll
        for (int it = 0; it < 4; it++) {
            uint32_t* d = &AsBase[(arow + it * 32) * APITCH + acol];
            d[0] = f32_to_tf32(av[it].x); d[1] = f32_to_tf32(av[it].y);
            d[2] = f32_to_tf32(av[it].z); d[3] = f32_to_tf32(av[it].w);
        }
#pragma unroll
        for (int it = 0; it < 2; it++) {
            uint32_t* d = &BsBase[(brow + it * 32) * APITCH + bcol];
            d[0] = f32_to_tf32(bv[it].x); d[1] = f32_to_tf32(bv[it].y);
            d[2] = f32_to_tf32(bv[it].z); d[3] = f32_to_tf32(bv[it].w);
        }
    }
    __syncthreads();

    int buf = 0;
    for (int k0 = 0; k0 < K; k0 += 32) {
        const bool has_next = (k0 + 32 < K);
        float4 av[4], bv[2];
        if (has_next) {
#pragma unroll
            for (int it = 0; it < 4; it++)
                av[it] = *(const float4*)&Ag[(size_t)(arow + it * 32) * K + k0 + 32 + acol];
#pragma unroll
            for (int it = 0; it < 2; it++)
                bv[it] = *(const float4*)&Bg[(size_t)(brow + it * 32) * K + k0 + 32 + bcol];
        }

        const uint32_t* As = AsBase + buf * AS_WORDS;
        const uint32_t* Bs = BsBase + buf * BS_WORDS;
#pragma unroll
        for (int ks = 0; ks < 4; ks++) {
            const int k8 = ks * 8;
            uint32_t a[2][4];
#pragma unroll
            for (int mt = 0; mt < 2; mt++) {
                int rb = wm * 32 + mt * 16;
                a[mt][0] = As[(rb + grp) * APITCH + k8 + tg];
                a[mt][1] = As[(rb + grp + 8) * APITCH + k8 + tg];
                a[mt][2] = As[(rb + grp) * APITCH + k8 + tg + 4];
                a[mt][3] = As[(rb + grp + 8) * APITCH + k8 + tg + 4];
            }
#pragma unroll
            for (int nt = 0; nt < 4; nt++) {
                int nb = wn * 32 + nt * 8;
                uint32_t b0 = Bs[(nb + grp) * APITCH + k8 + tg];
                uint32_t b1 = Bs[(nb + grp) * APITCH + k8 + tg + 4];
#pragma unroll
                for (int mt = 0; mt < 2; mt++)
                    mma_tf32_16x8x8(c[mt][nt][0], c[mt][nt][1],
                                    c[mt][nt][2], c[mt][nt][3],
                                    a[mt][0], a[mt][1], a[mt][2], a[mt][3],
                                    b0, b1);
            }
        }

        if (has_next) {
            uint32_t* Asn = AsBase + (buf ^ 1) * AS_WORDS;
            uint32_t* Bsn = BsBase + (buf ^ 1) * BS_WORDS;
#pragma unroll
            for (int it = 0; it < 4; it++) {
                uint32_t* d = &Asn[(arow + it * 32) * APITCH + acol];
                d[0] = f32_to_tf32(av[it].x); d[1] = f32_to_tf32(av[it].y);
                d[2] = f32_to_tf32(av[it].z); d[3] = f32_to_tf32(av[it].w);
            }
#pragma unroll
            for (int it = 0; it < 2; it++) {
                uint32_t* d = &Bsn[(brow + it * 32) * APITCH + bcol];
                d[0] = f32_to_tf32(bv[it].x); d[1] = f32_to_tf32(bv[it].y);
                d[2] = f32_to_tf32(bv[it].z); d[3] = f32_to_tf32(bv[it].w);
            }
            __syncthreads();
        }
        buf ^= 1;
    }

#pragma unroll
    for (int mt = 0; mt < 2; mt++) {
#pragma unroll
        for (int nt = 0; nt < 4; nt++) {
            int col = n0 + wn * 32 + nt * 8 + tg * 2;
            float b0 = bias[col], b1 = bias[col + 1];
            float s0 = (col     < scaleCols) ? scale : 1.f;
            float s1 = (col + 1 < scaleCols) ? scale : 1.f;
            int r0 = m0 + wm * 32 + mt * 16 + grp;
            float2 v0 = make_float2((c[mt][nt][0] + b0) * s0,
                                    (c[mt][nt][1] + b1) * s1);
            float2 v1 = make_float2((c[mt][nt][2] + b0) * s0,
                                    (c[mt][nt][3] + b1) * s1);
            *(float2*)&C[(size_t)r0 * N + col]       = v0;
            *(float2*)&C[(size_t)(r0 + 8) * N + col] = v1;
        }
    }
}

// ---------------------------------------------------------------------------
// Bias pre-gather
// ---------------------------------------------------------------------------
__global__ void bias_gather_kernel(const float* __restrict__ table,
                                   const int* __restrict__ pos)
{
    const int w = blockIdx.x, h = blockIdx.y;
    float* dst = g_biasg + (size_t)(h * TOW + w) * (NWIN * NWIN);
    for (int idx = threadIdx.x; idx < NWIN * NWIN; idx += blockDim.x) {
        int p = pos[idx];
        dst[idx] = table[((size_t)p * TOW + w) * NHEADS + h];
    }
}

// ---------------------------------------------------------------------------
// Tensor-core attention v3: one CTA per (b,w,h), 288 threads = 9 warps.
// Q/K/V mma fragments are loaded directly from global (L1-resident reuse);
// only the S/P buffer lives in smem (144x148 fp32 = 85KB) -> 2 CTAs/SM.
// ---------------------------------------------------------------------------
#define ATTN_THREADS 288
#define SP  148
#define ATTN_SMEM_B (NWIN * SP * 4)

__global__ __launch_bounds__(ATTN_THREADS, 2)
void attn_mma_kernel()
{
    extern __shared__ uint32_t smw[];
    float*    S  = (float*)smw;
    uint32_t* Su = smw;

    const int w = blockIdx.x, b = blockIdx.y, h = blockIdx.z;
    const int tid  = threadIdx.x;
    const int warp = tid >> 5, lane = tid & 31;
    const int grp  = lane >> 2, tg = lane & 3;
    const int rb   = warp * 16;

    const size_t base = (size_t)(b * TOW + w) * NWIN * QKV_N + h * HD;
    const float* __restrict__ Qg = g_qkv + base;
    const float* __restrict__ Kg = Qg + 192;
    const float* __restrict__ Vg = Qg + 384;

    // Q A-fragments for this warp's 16-row stripe (reused across all 18 n-tiles)
    uint32_t aq[4][4];
#pragma unroll
    for (int kt = 0; kt < 4; kt++) {
        const int k8 = kt * 8;
        aq[kt][0] = f32_to_tf32(Qg[(size_t)(rb + grp) * QKV_N + k8 + tg]);
        aq[kt][1] = f32_to_tf32(Qg[(size_t)(rb + grp + 8) * QKV_N + k8 + tg]);
        aq[kt][2] = f32_to_tf32(Qg[(size_t)(rb + grp) * QKV_N + k8 + tg + 4]);
        aq[kt][3] = f32_to_tf32(Qg[(size_t)(rb + grp + 8) * QKV_N + k8 + tg + 4]);
    }

    // S = Q K^T + bias
    const float* bptr = g_biasg + (size_t)(h * TOW + w) * (NWIN * NWIN);
#pragma unroll 2
    for (int nt = 0; nt < 18; nt++) {
        const int nb = nt * 8;
        float c0 = 0.f, c1 = 0.f, c2 = 0.f, c3 = 0.f;
#pragma unroll
        for (int kt = 0; kt < 4; kt++) {
            const int k8 = kt * 8;
            uint32_t b0 = f32_to_tf32(Kg[(size_t)(nb + grp) * QKV_N + k8 + tg]);
            uint32_t b1 = f32_to_tf32(Kg[(size_t)(nb + grp) * QKV_N + k8 + tg + 4]);
            mma_tf32_16x8x8(c0, c1, c2, c3,
                            aq[kt][0], aq[kt][1], aq[kt][2], aq[kt][3], b0, b1);
        }
        const int col = nb + tg * 2;
        float2 bv0 = *(const float2*)&bptr[(rb + grp) * NWIN + col];
        float2 bv1 = *(const float2*)&bptr[(rb + grp + 8) * NWIN + col];
        *(float2*)&S[(rb + grp) * SP + col]     = make_float2(c0 + bv0.x, c1 + bv0.y);
        *(float2*)&S[(rb + grp + 8) * SP + col] = make_float2(c2 + bv1.x, c3 + bv1.y);
    }
    __syncthreads();

    // Softmax per row (warp handles its 16 rows); write tf32 probabilities in-place
    for (int r = 0; r < 16; r++) {
        float* row = &S[(rb + r) * SP];
        float mx = -1e30f;
        for (int j = lane; j < NWIN; j += 32) mx = fmaxf(mx, row[j]);
#pragma unroll
        for (int o = 16; o; o >>= 1) mx = fmaxf(mx, __shfl_xor_sync(0xffffffffu, mx, o));
        float pv[5];
        float sum = 0.f;
        int cnt = 0;
        for (int j = lane; j < NWIN; j += 32) {
            float p = __expf(row[j] - mx);
            pv[cnt++] = p;
            sum += p;
        }
#pragma unroll
        for (int o = 16; o; o >>= 1) sum += __shfl_xor_sync(0xffffffffu, sum, o);
        float inv = 1.f / sum;
        cnt = 0;
        uint32_t* rowu = &Su[(rb + r) * SP];
        for (int j = lane; j < NWIN; j += 32) rowu[j] = f32_to_tf32(pv[cnt++] * inv);
    }
    __syncthreads();

    // O = P V  (warp: 16 rows x 32 cols, K = 144); V B-frags straight from global
    float c[4][4];
#pragma unroll
    for (int nt = 0; nt < 4; nt++)
#pragma unroll
        for (int r = 0; r < 4; r++) c[nt][r] = 0.f;

#pragma unroll 3
    for (int kk = 0; kk < 18; kk++) {
        const int k8 = kk * 8;
        uint32_t a0 = Su[(rb + grp) * SP + k8 + tg];
        uint32_t a1 = Su[(rb + grp + 8) * SP + k8 + tg];
        uint32_t a2 = Su[(rb + grp) * SP + k8 + tg + 4];
        uint32_t a3 = Su[(rb + grp + 8) * SP + k8 + tg + 4];
#pragma unroll
        for (int nt = 0; nt < 4; nt++) {
            uint32_t b0 = f32_to_tf32(Vg[(size_t)(k8 + tg) * QKV_N + nt * 8 + grp]);
            uint32_t b1 = f32_to_tf32(Vg[(size_t)(k8 + tg + 4) * QKV_N + nt * 8 + grp]);
            mma_tf32_16x8x8(c[nt][0], c[nt][1], c[nt][2], c[nt][3],
                            a0, a1, a2, a3, b0, b1);
        }
    }

    const size_t obase = (size_t)(b * TOW + w) * NWIN * DIMC + h * HD;
#pragma unroll
    for (int nt = 0; nt < 4; nt++) {
        const int col = nt * 8 + tg * 2;
        *(float2*)&g_att[obase + (size_t)(rb + grp) * DIMC + col] =
            make_float2(c[nt][0], c[nt][1]);
        *(float2*)&g_att[obase + (size_t)(rb + grp + 8) * DIMC + col] =
            make_float2(c[nt][2], c[nt][3]);
    }
}

// ---------------------------------------------------------------------------
extern "C" void kernel_launch(void* const* d_in, const int* in_sizes, int n_in,
                              void* d_out, int out_size)
{
    const float* x      = (const float*)d_in[0];
    const float* qkv_w  = (const float*)d_in[1];
    const float* qkv_b  = (const float*)d_in[2];
    const float* proj_w = (const float*)d_in[3];
    const float* proj_b = (const float*)d_in[4];
    const float* table  = (const float*)d_in[5];
    const int*   pos    = (const int*)d_in[6];
    float* out = (float*)d_out;

    float *qkv_s, *att_s;
    cudaGetSymbolAddress((void**)&qkv_s, g_qkv);
    cudaGetSymbolAddress((void**)&att_s, g_att);

    cudaFuncSetAttribute(gemm_mma_kernel, cudaFuncAttributeMaxDynamicSharedMemorySize,
                         GEMM_SMEM_B);
    cudaFuncSetAttribute(attn_mma_kernel, cudaFuncAttributeMaxDynamicSharedMemorySize,
                         ATTN_SMEM_B);

    // 1) fused QKV projection (mma.sync tf32; +bias, q scaled)
    {
        dim3 grid(QKV_N / 64, MTOT / 128);
        gemm_mma_kernel<<<grid, 256, GEMM_SMEM_B>>>(x, qkv_w, qkv_b, qkv_s,
                                                    QKV_N, DIMC, DIMC, ATT_SCALE);
    }
    // 2) bias pre-gather
    {
        dim3 grid(TOW, NHEADS);
        bias_gather_kernel<<<grid, 256>>>(table, pos);
    }
    // 3) windowed attention (tensor-core, smem = S only)
    {
        dim3 grid(TOW, BATCH, NHEADS);
        attn_mma_kernel<<<grid, ATTN_THREADS, ATTN_SMEM_B>>>();
    }
    // 4) output projection (mma.sync tf32)
    {
        dim3 grid(DIMC / 64, MTOT / 128);
        gemm_mma_kernel<<<grid, 256, GEMM_SMEM_B>>>(att_s, proj_w, proj_b, out,
                                                    DIMC, DIMC, 0, 1.0f);
    }
}

// round 6
// speedup vs baseline: 2.4210x; 1.0131x over previous
#include <cuda_runtime.h>
#include <cuda_bf16.h>
#include <cstdint>

// Problem constants
#define DIMC    192
#define QKV_N   576
#define NWIN    144
#define NHEADS  6
#define HD      32
#define TOW     64
#define BATCH   30
#define MTOT    (BATCH * TOW * NWIN)   // 276480 rows
#define ATT_SCALE 0.17677669529663687f

// Scratch
static __device__ float g_qkv[(size_t)MTOT * QKV_N];
static __device__ float g_att[(size_t)MTOT * DIMC];
static __device__ float g_biasg[(size_t)NHEADS * TOW * NWIN * NWIN];

// ---------------------------------------------------------------------------
// tf32 mma.sync helpers (tcgen05 unavailable: harness builds compute_103 PTX)
// ---------------------------------------------------------------------------
__device__ __forceinline__ uint32_t f32_to_tf32(float x) {
    uint32_t r;
    asm("cvt.rna.tf32.f32 %0, %1;" : "=r"(r) : "f"(x));
    return r;
}

__device__ __forceinline__ void mma_tf32_16x8x8(
    float& c0, float& c1, float& c2, float& c3,
    uint32_t a0, uint32_t a1, uint32_t a2, uint32_t a3,
    uint32_t b0, uint32_t b1)
{
    asm volatile(
        "mma.sync.aligned.m16n8k8.row.col.f32.tf32.tf32.f32 "
        "{%0,%1,%2,%3}, {%4,%5,%6,%7}, {%8,%9}, {%0,%1,%2,%3};"
        : "+f"(c0), "+f"(c1), "+f"(c2), "+f"(c3)
        : "r"(a0), "r"(a1), "r"(a2), "r"(a3), "r"(b0), "r"(b1));
}

// ---------------------------------------------------------------------------
// tf32 mma.sync GEMM, double-buffered smem (unchanged from R5).
// C[M,N] = A[M,K] @ B[N,K]^T + bias[N]; cols<scaleCols *= scale
// ---------------------------------------------------------------------------
#define APITCH 36
#define AS_WORDS (128 * APITCH)
#define BS_WORDS (64 * APITCH)
#define GEMM_SMEM_B ((2 * AS_WORDS + 2 * BS_WORDS) * 4)

__global__ __launch_bounds__(256, 2)
void gemm_mma_kernel(const float* __restrict__ A, const float* __restrict__ B,
                     const float* __restrict__ bias, float* __restrict__ C,
                     int N, int K, int scaleCols, float scale)
{
    extern __shared__ uint32_t gsm[];
    uint32_t* AsBase = gsm;
    uint32_t* BsBase = gsm + 2 * AS_WORDS;

    const int tid  = threadIdx.x;
    const int warp = tid >> 5, lane = tid & 31;
    const int wm   = warp & 3, wn = warp >> 2;
    const int grp  = lane >> 2, tg = lane & 3;
    const int n0   = blockIdx.x * 64;
    const int m0   = blockIdx.y * 128;

    float c[2][4][4];
#pragma unroll
    for (int mt = 0; mt < 2; mt++)
#pragma unroll
        for (int nt = 0; nt < 4; nt++)
#pragma unroll
            for (int r = 0; r < 4; r++) c[mt][nt][r] = 0.f;

    const float* Ag = A + (size_t)m0 * K;
    const float* Bg = B + (size_t)n0 * K;

    const int arow = tid >> 3, acol = (tid & 7) * 4;
    const int brow = tid >> 3, bcol = (tid & 7) * 4;

    {
        float4 av[4], bv[2];
#pragma unroll
        for (int it = 0; it < 4; it++)
            av[it] = *(const float4*)&Ag[(size_t)(arow + it * 32) * K + acol];
#pragma unroll
        for (int it = 0; it < 2; it++)
            bv[it] = *(const float4*)&Bg[(size_t)(brow + it * 32) * K + bcol];
#pragma unroll
        for (int it = 0; it < 4; it++) {
            uint32_t* d = &AsBase[(arow + it * 32) * APITCH + acol];
            d[0] = f32_to_tf32(av[it].x); d[1] = f32_to_tf32(av[it].y);
            d[2] = f32_to_tf32(av[it].z); d[3] = f32_to_tf32(av[it].w);
        }
#pragma unroll
        for (int it = 0; it < 2; it++) {
            uint32_t* d = &BsBase[(brow + it * 32) * APITCH + bcol];
            d[0] = f32_to_tf32(bv[it].x); d[1] = f32_to_tf32(bv[it].y);
            d[2] = f32_to_tf32(bv[it].z); d[3] = f32_to_tf32(bv[it].w);
        }
    }
    __syncthreads();

    int buf = 0;
    for (int k0 = 0; k0 < K; k0 += 32) {
        const bool has_next = (k0 + 32 < K);
        float4 av[4], bv[2];
        if (has_next) {
#pragma unroll
            for (int it = 0; it < 4; it++)
                av[it] = *(const float4*)&Ag[(size_t)(arow + it * 32) * K + k0 + 32 + acol];
#pragma unroll
            for (int it = 0; it < 2; it++)
                bv[it] = *(const float4*)&Bg[(size_t)(brow + it * 32) * K + k0 + 32 + bcol];
        }

        const uint32_t* As = AsBase + buf * AS_WORDS;
        const uint32_t* Bs = BsBase + buf * BS_WORDS;
#pragma unroll
        for (int ks = 0; ks < 4; ks++) {
            const int k8 = ks * 8;
            uint32_t a[2][4];
#pragma unroll
            for (int mt = 0; mt < 2; mt++) {
                int rb = wm * 32 + mt * 16;
                a[mt][0] = As[(rb + grp) * APITCH + k8 + tg];
                a[mt][1] = As[(rb + grp + 8) * APITCH + k8 + tg];
                a[mt][2] = As[(rb + grp) * APITCH + k8 + tg + 4];
                a[mt][3] = As[(rb + grp + 8) * APITCH + k8 + tg + 4];
            }
#pragma unroll
            for (int nt = 0; nt < 4; nt++) {
                int nb = wn * 32 + nt * 8;
                uint32_t b0 = Bs[(nb + grp) * APITCH + k8 + tg];
                uint32_t b1 = Bs[(nb + grp) * APITCH + k8 + tg + 4];
#pragma unroll
                for (int mt = 0; mt < 2; mt++)
                    mma_tf32_16x8x8(c[mt][nt][0], c[mt][nt][1],
                                    c[mt][nt][2], c[mt][nt][3],
                                    a[mt][0], a[mt][1], a[mt][2], a[mt][3],
                                    b0, b1);
            }
        }

        if (has_next) {
            uint32_t* Asn = AsBase + (buf ^ 1) * AS_WORDS;
            uint32_t* Bsn = BsBase + (buf ^ 1) * BS_WORDS;
#pragma unroll
            for (int it = 0; it < 4; it++) {
                uint32_t* d = &Asn[(arow + it * 32) * APITCH + acol];
                d[0] = f32_to_tf32(av[it].x); d[1] = f32_to_tf32(av[it].y);
                d[2] = f32_to_tf32(av[it].z); d[3] = f32_to_tf32(av[it].w);
            }
#pragma unroll
            for (int it = 0; it < 2; it++) {
                uint32_t* d = &Bsn[(brow + it * 32) * APITCH + bcol];
                d[0] = f32_to_tf32(bv[it].x); d[1] = f32_to_tf32(bv[it].y);
                d[2] = f32_to_tf32(bv[it].z); d[3] = f32_to_tf32(bv[it].w);
            }
            __syncthreads();
        }
        buf ^= 1;
    }

#pragma unroll
    for (int mt = 0; mt < 2; mt++) {
#pragma unroll
        for (int nt = 0; nt < 4; nt++) {
            int col = n0 + wn * 32 + nt * 8 + tg * 2;
            float b0 = bias[col], b1 = bias[col + 1];
            float s0 = (col     < scaleCols) ? scale : 1.f;
            float s1 = (col + 1 < scaleCols) ? scale : 1.f;
            int r0 = m0 + wm * 32 + mt * 16 + grp;
            float2 v0 = make_float2((c[mt][nt][0] + b0) * s0,
                                    (c[mt][nt][1] + b1) * s1);
            float2 v1 = make_float2((c[mt][nt][2] + b0) * s0,
                                    (c[mt][nt][3] + b1) * s1);
            *(float2*)&C[(size_t)r0 * N + col]       = v0;
            *(float2*)&C[(size_t)(r0 + 8) * N + col] = v1;
        }
    }
}

// ---------------------------------------------------------------------------
// Bias pre-gather
// ---------------------------------------------------------------------------
__global__ void bias_gather_kernel(const float* __restrict__ table,
                                   const int* __restrict__ pos)
{
    const int w = blockIdx.x, h = blockIdx.y;
    float* dst = g_biasg + (size_t)(h * TOW + w) * (NWIN * NWIN);
    for (int idx = threadIdx.x; idx < NWIN * NWIN; idx += blockDim.x) {
        int p = pos[idx];
        dst[idx] = table[((size_t)p * TOW + w) * NHEADS + h];
    }
}

// ---------------------------------------------------------------------------
// Tensor-core attention v4: one CTA per (b,w,h,seg), seg = 48 query rows.
// 96 threads = 3 warps x 16 rows. S smem = 48x148 fp32 = 27.8KB -> ~8 CTAs/SM.
// Q/K/V frags straight from global (L1/L2-resident across the 3 segs).
// ---------------------------------------------------------------------------
#define ATTN_THREADS 96
#define SEG_ROWS 48
#define NSEG 3
#define SP  148
#define ATTN_SMEM_B (SEG_ROWS * SP * 4)

__global__ __launch_bounds__(ATTN_THREADS)
void attn_mma_kernel()
{
    extern __shared__ uint32_t smw[];
    float*    S  = (float*)smw;
    uint32_t* Su = smw;

    const int w = blockIdx.x, b = blockIdx.y;
    const int h = blockIdx.z / NSEG, seg = blockIdx.z % NSEG;
    const int tid  = threadIdx.x;
    const int warp = tid >> 5, lane = tid & 31;
    const int grp  = lane >> 2, tg = lane & 3;
    const int lrb  = warp * 16;              // local row base in S
    const int rb   = seg * SEG_ROWS + lrb;   // global query row base

    const size_t base = (size_t)(b * TOW + w) * NWIN * QKV_N + h * HD;
    const float* __restrict__ Qg = g_qkv + base;
    const float* __restrict__ Kg = Qg + 192;
    const float* __restrict__ Vg = Qg + 384;

    // Q A-fragments for this warp's 16 rows (reused across all 18 n-tiles)
    uint32_t aq[4][4];
#pragma unroll
    for (int kt = 0; kt < 4; kt++) {
        const int k8 = kt * 8;
        aq[kt][0] = f32_to_tf32(Qg[(size_t)(rb + grp) * QKV_N + k8 + tg]);
        aq[kt][1] = f32_to_tf32(Qg[(size_t)(rb + grp + 8) * QKV_N + k8 + tg]);
        aq[kt][2] = f32_to_tf32(Qg[(size_t)(rb + grp) * QKV_N + k8 + tg + 4]);
        aq[kt][3] = f32_to_tf32(Qg[(size_t)(rb + grp + 8) * QKV_N + k8 + tg + 4]);
    }

    // S = Q K^T + bias  (16 rows x 144 cols per warp)
    const float* bptr = g_biasg + (size_t)(h * TOW + w) * (NWIN * NWIN);
#pragma unroll 3
    for (int nt = 0; nt < 18; nt++) {
        const int nb = nt * 8;
        float c0 = 0.f, c1 = 0.f, c2 = 0.f, c3 = 0.f;
#pragma unroll
        for (int kt = 0; kt < 4; kt++) {
            const int k8 = kt * 8;
            uint32_t b0 = f32_to_tf32(Kg[(size_t)(nb + grp) * QKV_N + k8 + tg]);
            uint32_t b1 = f32_to_tf32(Kg[(size_t)(nb + grp) * QKV_N + k8 + tg + 4]);
            mma_tf32_16x8x8(c0, c1, c2, c3,
                            aq[kt][0], aq[kt][1], aq[kt][2], aq[kt][3], b0, b1);
        }
        const int col = nb + tg * 2;
        float2 bv0 = *(const float2*)&bptr[(rb + grp) * NWIN + col];
        float2 bv1 = *(const float2*)&bptr[(rb + grp + 8) * NWIN + col];
        *(float2*)&S[(lrb + grp) * SP + col]     = make_float2(c0 + bv0.x, c1 + bv0.y);
        *(float2*)&S[(lrb + grp + 8) * SP + col] = make_float2(c2 + bv1.x, c3 + bv1.y);
    }
    __syncthreads();

    // Softmax per row; write tf32 probabilities in-place
    for (int r = 0; r < 16; r++) {
        float* row = &S[(lrb + r) * SP];
        float mx = -1e30f;
        for (int j = lane; j < NWIN; j += 32) mx = fmaxf(mx, row[j]);
#pragma unroll
        for (int o = 16; o; o >>= 1) mx = fmaxf(mx, __shfl_xor_sync(0xffffffffu, mx, o));
        float pv[5];
        float sum = 0.f;
        int cnt = 0;
        for (int j = lane; j < NWIN; j += 32) {
            float p = __expf(row[j] - mx);
            pv[cnt++] = p;
            sum += p;
        }
#pragma unroll
        for (int o = 16; o; o >>= 1) sum += __shfl_xor_sync(0xffffffffu, sum, o);
        float inv = 1.f / sum;
        cnt = 0;
        uint32_t* rowu = &Su[(lrb + r) * SP];
        for (int j = lane; j < NWIN; j += 32) rowu[j] = f32_to_tf32(pv[cnt++] * inv);
    }
    __syncthreads();

    // O = P V  (warp: 16 rows x 32 cols, K = 144); V B-frags from global
    float c[4][4];
#pragma unroll
    for (int nt = 0; nt < 4; nt++)
#pragma unroll
        for (int r = 0; r < 4; r++) c[nt][r] = 0.f;

#pragma unroll 3
    for (int kk = 0; kk < 18; kk++) {
        const int k8 = kk * 8;
        uint32_t a0 = Su[(lrb + grp) * SP + k8 + tg];
        uint32_t a1 = Su[(lrb + grp + 8) * SP + k8 + tg];
        uint32_t a2 = Su[(lrb + grp) * SP + k8 + tg + 4];
        uint32_t a3 = Su[(lrb + grp + 8) * SP + k8 + tg + 4];
#pragma unroll
        for (int nt = 0; nt < 4; nt++) {
            uint32_t b0 = f32_to_tf32(Vg[(size_t)(k8 + tg) * QKV_N + nt * 8 + grp]);
            uint32_t b1 = f32_to_tf32(Vg[(size_t)(k8 + tg + 4) * QKV_N + nt * 8 + grp]);
            mma_tf32_16x8x8(c[nt][0], c[nt][1], c[nt][2], c[nt][3],
                            a0, a1, a2, a3, b0, b1);
        }
    }

    const size_t obase = (size_t)(b * TOW + w) * NWIN * DIMC + h * HD;
#pragma unroll
    for (int nt = 0; nt < 4; nt++) {
        const int col = nt * 8 + tg * 2;
        *(float2*)&g_att[obase + (size_t)(rb + grp) * DIMC + col] =
            make_float2(c[nt][0], c[nt][1]);
        *(float2*)&g_att[obase + (size_t)(rb + grp + 8) * DIMC + col] =
            make_float2(c[nt][2], c[nt][3]);
    }
}

// ---------------------------------------------------------------------------
extern "C" void kernel_launch(void* const* d_in, const int* in_sizes, int n_in,
                              void* d_out, int out_size)
{
    const float* x      = (const float*)d_in[0];
    const float* qkv_w  = (const float*)d_in[1];
    const float* qkv_b  = (const float*)d_in[2];
    const float* proj_w = (const float*)d_in[3];
    const float* proj_b = (const float*)d_in[4];
    const float* table  = (const float*)d_in[5];
    const int*   pos    = (const int*)d_in[6];
    float* out = (float*)d_out;

    float *qkv_s, *att_s;
    cudaGetSymbolAddress((void**)&qkv_s, g_qkv);
    cudaGetSymbolAddress((void**)&att_s, g_att);

    cudaFuncSetAttribute(gemm_mma_kernel, cudaFuncAttributeMaxDynamicSharedMemorySize,
                         GEMM_SMEM_B);
    cudaFuncSetAttribute(attn_mma_kernel, cudaFuncAttributeMaxDynamicSharedMemorySize,
                         ATTN_SMEM_B);

    // 1) fused QKV projection (mma.sync tf32; +bias, q scaled)
    {
        dim3 grid(QKV_N / 64, MTOT / 128);
        gemm_mma_kernel<<<grid, 256, GEMM_SMEM_B>>>(x, qkv_w, qkv_b, qkv_s,
                                                    QKV_N, DIMC, DIMC, ATT_SCALE);
    }
    // 2) bias pre-gather
    {
        dim3 grid(TOW, NHEADS);
        bias_gather_kernel<<<grid, 256>>>(table, pos);
    }
    // 3) windowed attention (48-row segments, high occupancy)
    {
        dim3 grid(TOW, BATCH, NHEADS * NSEG);
        attn_mma_kernel<<<grid, ATTN_THREADS, ATTN_SMEM_B>>>();
    }
    // 4) output projection (mma.sync tf32)
    {
        dim3 grid(DIMC / 64, MTOT / 128);
        gemm_mma_kernel<<<grid, 256, GEMM_SMEM_B>>>(att_s, proj_w, proj_b, out,
                                                    DIMC, DIMC, 0, 1.0f);
    }
}